// round 6
// baseline (speedup 1.0000x reference)
#include <cuda_runtime.h>
#include <cuda_bf16.h>
#include <math.h>
#include <stdint.h>

#define N_TOT 2048
#define T_SEQ 70
#define HID   230
#define DIN   60
#define EMB_W 50
#define NBAG  64
#define BAGSZ 32
#define NREL  100

// GRU step: M=128, N=96 (32j x 3 gates), K=320 (2 emb chunks + 8 h chunks of 32)
// stage: A_hi[128*64B] A_lo B_hi[96*64B] B_lo, XOR-swizzled 64B rows
#define NTHREADS 384
#define STAGE_B  28672
#define A_LO_OFF 8192
#define B_HI_OFF 16384
#define DUMP_OFF (3 * STAGE_B)            // 86016
#define SMEM_DYN (DUMP_OFF + 32 * 132 * 4) // 102912

// ---------------- device scratch ----------------
__device__ __align__(128) __nv_bfloat16 g_Wt[(size_t)2 * 8 * 2 * 10 * 96 * 32]; // [dir][jt][part][chunk][96][32]
__device__ __align__(128) __nv_bfloat16 g_embsp[(size_t)T_SEQ * 2 * N_TOT * 64]; // [t][part][n][64]
__device__ __align__(128) __nv_bfloat16 g_hbf[(size_t)2 * 2 * 2 * N_TOT * 256];  // [buf][dir][part][n][256]
__device__ float g_hT[(size_t)2 * 2 * 256 * N_TOT];                               // [buf][dir][j][n]
__device__ float g_tup[(size_t)2 * T_SEQ * N_TOT * HID];                          // [dir][t][n][j]
__device__ float g_repre[N_TOT * HID];
__device__ float g_sen_s[NBAG * HID];
__device__ float g_loss_part[NBAG];

// ---------------- ptx helpers ----------------
__device__ __forceinline__ uint32_t smem_u32(const void *p) {
    uint32_t a;
    asm("{ .reg .u64 t; cvta.to.shared.u64 t, %1; cvt.u32.u64 %0, t; }" : "=r"(a) : "l"(p));
    return a;
}
__device__ __forceinline__ void cpa16(uint32_t dst, const void *src) {
    asm volatile("cp.async.ca.shared.global [%0], [%1], 16;" :: "r"(dst), "l"(src));
}
#define CP_COMMIT() asm volatile("cp.async.commit_group;" ::: "memory")
#define CP_WAIT1()  asm volatile("cp.async.wait_group 1;" ::: "memory")
#define CP_WAIT0()  asm volatile("cp.async.wait_group 0;" ::: "memory")
#define LDSM4(r, a)                                                                   \
    asm volatile("ldmatrix.sync.aligned.m8n8.x4.shared.b16 {%0,%1,%2,%3}, [%4];"      \
                 : "=r"((r)[0]), "=r"((r)[1]), "=r"((r)[2]), "=r"((r)[3]) : "r"(a))
#define MMA16816(c, a, b0, b1)                                                        \
    asm volatile("mma.sync.aligned.m16n8k16.row.col.f32.bf16.bf16.f32 "               \
                 "{%0,%1,%2,%3},{%4,%5,%6,%7},{%8,%9},{%0,%1,%2,%3};"                 \
                 : "+f"((c)[0]), "+f"((c)[1]), "+f"((c)[2]), "+f"((c)[3])             \
                 : "r"((a)[0]), "r"((a)[1]), "r"((a)[2]), "r"((a)[3]), "r"(b0), "r"(b1))

__device__ __forceinline__ uint32_t pack2(__nv_bfloat16 a, __nv_bfloat16 b) {
    unsigned short ra = *(unsigned short *)&a, rb = *(unsigned short *)&b;
    return (uint32_t)ra | ((uint32_t)rb << 16);
}
__device__ __forceinline__ uint32_t swz(int row, int seg) {
    return (uint32_t)row * 64u + (uint32_t)((seg ^ ((row >> 1) & 3)) << 4);
}

// ---------------- prep kernels ----------------
__global__ void zero_kernel() {
    size_t i = (size_t)blockIdx.x * blockDim.x + threadIdx.x;
    size_t nh = (size_t)2 * 2 * 2 * N_TOT * 256 / 2;
    if (i < nh) ((uint32_t *)g_hbf)[i] = 0u;
    if (i < (size_t)2 * 2 * 256 * N_TOT) g_hT[i] = 0.f;
}

// weights -> [dir][jt][part][chunk(10)][row 96][k 32], row = j_local*3 + gate
__global__ void prep_w_kernel(const float *__restrict__ Wihf, const float *__restrict__ Whhf,
                              const float *__restrict__ Wihb, const float *__restrict__ Whhb) {
    int idx = blockIdx.x * blockDim.x + threadIdx.x;
    if (idx >= 2 * 8 * 10 * 96 * 32) return;
    int kc = idx & 31;
    int r = (idx >> 5) % 96;
    int rest = idx / (96 * 32);
    int c = rest % 10;
    int jt = (rest / 10) & 7;
    int dir = rest / 80;
    const float *Wih = dir ? Wihb : Wihf;
    const float *Whh = dir ? Whhb : Whhf;
    int j = jt * 32 + r / 3;
    int g = r % 3;
    float v = 0.f;
    if (j < HID) {
        if (c < 2) {
            int k = c * 32 + kc;
            if (k < DIN) v = Wih[(g * HID + j) * DIN + k];
        } else {
            int kh = (c - 2) * 32 + kc;
            if (kh < HID) v = Whh[(g * HID + j) * HID + kh];
        }
    }
    __nv_bfloat16 hi = __float2bfloat16(v);
    __nv_bfloat16 lo = __float2bfloat16(v - __bfloat162float(hi));
    size_t i0 = ((((size_t)(dir * 8 + jt) * 2 + 0) * 10 + c) * 96 + r) * 32 + kc;
    size_t i1 = ((((size_t)(dir * 8 + jt) * 2 + 1) * 10 + c) * 96 + r) * 32 + kc;
    g_Wt[i0] = hi;
    g_Wt[i1] = lo;
}

__global__ void gather_kernel(const int *__restrict__ sent, const int *__restrict__ p1,
                              const int *__restrict__ p2, const float *__restrict__ wemb,
                              const float *__restrict__ p1t, const float *__restrict__ p2t) {
    size_t idx = (size_t)blockIdx.x * blockDim.x + threadIdx.x;
    if (idx >= (size_t)N_TOT * T_SEQ * 64) return;
    int k = (int)(idx & 63);
    size_t nt = idx >> 6;
    int t = (int)(nt % T_SEQ);
    int n = (int)(nt / T_SEQ);
    float v = 0.f;
    if (k < EMB_W) v = wemb[(size_t)sent[n * T_SEQ + t] * EMB_W + k];
    else if (k < EMB_W + 5) v = p1t[p1[n * T_SEQ + t] * 5 + (k - EMB_W)];
    else if (k < DIN) v = p2t[p2[n * T_SEQ + t] * 5 + (k - EMB_W - 5)];
    __nv_bfloat16 hi = __float2bfloat16(v);
    __nv_bfloat16 lo = __float2bfloat16(v - __bfloat162float(hi));
    g_embsp[((size_t)(t * 2 + 0) * N_TOT + n) * 64 + k] = hi;
    g_embsp[((size_t)(t * 2 + 1) * N_TOT + n) * 64 + k] = lo;
}

// ---------------- GRU step (mma.sync bf16, 3-pass split, 12 warps) ----------
__global__ void __launch_bounds__(NTHREADS, 2) gru_step_kernel(
    int s,
    const float *__restrict__ bihf, const float *__restrict__ bhhf,
    const float *__restrict__ bihb, const float *__restrict__ bhhb) {
    extern __shared__ char dsm[];
    const int dir = blockIdx.z;
    const int t = dir ? (T_SEQ - 1 - s) : s;
    const int n0 = blockIdx.x * 128;
    const int jt = blockIdx.y;
    const int tid = threadIdx.x;
    const int lane = tid & 31, wid = tid >> 5;
    const int warpM = wid & 3, warpN = wid >> 2;   // warpN in 0..2 (32 cols each)
    const int bufi = s & 1, bufo = (s + 1) & 1;
    const float *bih = dir ? bihb : bihf;
    const float *bhh = dir ? bhhb : bhhf;

    const uint32_t base = smem_u32(dsm);
    float *dumpIN = (float *)(dsm + DUMP_OFF);
    __shared__ float bs[4][32];
    if (tid < 32) {
        int j = jt * 32 + tid;
        bool ok = j < HID;
        bs[0][tid] = ok ? (bih[j] + bhh[j]) : 0.f;
        bs[1][tid] = ok ? (bih[HID + j] + bhh[HID + j]) : 0.f;
        bs[2][tid] = ok ? bih[2 * HID + j] : 0.f;
        bs[3][tid] = ok ? bhh[2 * HID + j] : 0.f;
    }

    const __nv_bfloat16 *embp = g_embsp + (size_t)t * 2 * N_TOT * 64 + (size_t)n0 * 64;
    const __nv_bfloat16 *hbfp = g_hbf + (size_t)((bufi * 2 + dir) * 2) * N_TOT * 256 + (size_t)n0 * 256;
    const __nv_bfloat16 *wbase = g_Wt + (size_t)(dir * 8 + jt) * 2 * 10 * (96 * 32);

    auto issue = [&](int c) {
        uint32_t st = base + (uint32_t)(c % 3) * STAGE_B;
#pragma unroll
        for (int part = 0; part < 2; part++) {
            const __nv_bfloat16 *Ap;
            int strideA;
            if (c < 2) { Ap = embp + (size_t)part * N_TOT * 64 + c * 32; strideA = 64; }
            else { Ap = hbfp + (size_t)part * N_TOT * 256 + (c - 2) * 32; strideA = 256; }
            // A: 128 rows x 4 segs = 512 items over 384 threads
            {
                int row = tid >> 2, seg = tid & 3;
                cpa16(st + part * A_LO_OFF + swz(row, seg), Ap + (size_t)row * strideA + seg * 8);
                int l = NTHREADS + tid;
                if (l < 512) {
                    row = l >> 2; seg = l & 3;
                    cpa16(st + part * A_LO_OFF + swz(row, seg), Ap + (size_t)row * strideA + seg * 8);
                }
            }
            // B: 96 rows x 4 segs = 384 items, one per thread
            const __nv_bfloat16 *Bp = wbase + (size_t)(part * 10 + c) * (96 * 32);
            {
                int row = tid >> 2, seg = tid & 3;
                cpa16(st + B_HI_OFF + part * 6144 + swz(row, seg), Bp + row * 32 + seg * 8);
            }
        }
        CP_COMMIT();
    };

    issue(0);
    issue(1);

    float acc[2][4][4];   // [mi][np*2+cp][frag]
#pragma unroll
    for (int mi = 0; mi < 2; mi++)
#pragma unroll
        for (int ni = 0; ni < 4; ni++)
#pragma unroll
            for (int q = 0; q < 4; q++) acc[mi][ni][q] = 0.f;

    const int laneR = lane & 15;
    const int laneHi = lane >> 4;
    const int gr = lane >> 2, lc = lane & 3;

    for (int c = 0; c < 10; c++) {
        if (c < 9) CP_WAIT1(); else CP_WAIT0();
        __syncthreads();
        if (c + 2 < 10) issue(c + 2);
        uint32_t sA = base + (uint32_t)(c % 3) * STAGE_B;
        uint32_t sB = sA + B_HI_OFF;
#pragma unroll
        for (int ks = 0; ks < 2; ks++) {
            uint32_t ah[2][4], al[2][4];
#pragma unroll
            for (int mi = 0; mi < 2; mi++) {
                int row = warpM * 32 + mi * 16 + laneR;
                uint32_t off = swz(row, ks * 2 + laneHi);
                LDSM4(ah[mi], sA + off);
                LDSM4(al[mi], sA + A_LO_OFF + off);
            }
#pragma unroll
            for (int np = 0; np < 2; np++) {
                int row = warpN * 32 + np * 16 + laneR;
                uint32_t off = swz(row, ks * 2 + laneHi);
                uint32_t bh[4], bl[4];
                LDSM4(bh, sB + off);
                LDSM4(bl, sB + 6144 + off);
#pragma unroll
                for (int mi = 0; mi < 2; mi++) {
                    float *c0 = acc[mi][np * 2];
                    float *c1 = acc[mi][np * 2 + 1];
                    MMA16816(c0, ah[mi], bh[0], bh[2]);
                    MMA16816(c0, ah[mi], bl[0], bl[2]);
                    MMA16816(c0, al[mi], bh[0], bh[2]);
                    MMA16816(c1, ah[mi], bh[1], bh[3]);
                    MMA16816(c1, ah[mi], bl[1], bl[3]);
                    MMA16816(c1, al[mi], bh[1], bh[3]);
                }
            }
        }
        if (c == 1) {
            // emb phase done: move i_n slots (col%3==2) to dumpIN, zero them
#pragma unroll
            for (int mi = 0; mi < 2; mi++)
#pragma unroll
                for (int ni = 0; ni < 4; ni++)
#pragma unroll
                    for (int b = 0; b < 2; b++) {
                        int col = warpN * 32 + ni * 8 + lc * 2 + b;
                        if (col % 3 == 2) {
                            int jl = col / 3;
                            int m0 = warpM * 32 + mi * 16 + gr;
                            dumpIN[jl * 132 + m0] = acc[mi][ni][b];
                            dumpIN[jl * 132 + m0 + 8] = acc[mi][ni][b + 2];
                            acc[mi][ni][b] = 0.f;
                            acc[mi][ni][b + 2] = 0.f;
                        }
                    }
        }
    }

    __syncthreads();
    float *D2 = (float *)dsm;   // [96 col][132]
#pragma unroll
    for (int mi = 0; mi < 2; mi++)
#pragma unroll
        for (int ni = 0; ni < 4; ni++) {
            int col0 = warpN * 32 + ni * 8 + lc * 2;
            int m0 = warpM * 32 + mi * 16 + gr;
            D2[col0 * 132 + m0] = acc[mi][ni][0];
            D2[(col0 + 1) * 132 + m0] = acc[mi][ni][1];
            D2[col0 * 132 + m0 + 8] = acc[mi][ni][2];
            D2[(col0 + 1) * 132 + m0 + 8] = acc[mi][ni][3];
        }
    __syncthreads();

    // gates: 256 work items (32 jl x 8 nsegs of 16)
    if (tid < 256) {
        int jl = tid >> 3, nseg = tid & 7;
        int j = jt * 32 + jl;
        int nb = nseg * 16;
        float br = bs[0][jl], bz = bs[1][jl], bin = bs[2][jl], bhn = bs[3][jl];
        const float *holdp = g_hT + ((size_t)(bufi * 2 + dir) * 256 + j) * N_TOT + n0 + nb;
        float *hnewp = g_hT + ((size_t)(bufo * 2 + dir) * 256 + j) * N_TOT + n0 + nb;
        const float *Dr = D2 + (jl * 3 + 0) * 132 + nb;
        const float *Dz = D2 + (jl * 3 + 1) * 132 + nb;
        const float *Dn = D2 + (jl * 3 + 2) * 132 + nb;
        const float *Di = dumpIN + jl * 132 + nb;
        float hv[16];
#pragma unroll
        for (int i = 0; i < 16; i++) {
            float r = 1.f / (1.f + expf(-(Dr[i] + br)));
            float z = 1.f / (1.f + expf(-(Dz[i] + bz)));
            float nn = tanhf(Di[i] + bin + r * (Dn[i] + bhn));
            float h = (1.f - z) * nn + z * holdp[i];
            hv[i] = h;
            hnewp[i] = h;
        }
#pragma unroll
        for (int i = 0; i < 16; i++) D2[(jl * 3) * 132 + nb + i] = hv[i];
    }
    __syncthreads();

    // transposed writeout: tup fp32 [n][j], hbf hi/lo [part][n][256]; 512 items
    {
        __nv_bfloat16 *hbo = g_hbf + (size_t)((bufo * 2 + dir) * 2) * N_TOT * 256;
        float *tupp = g_tup + (((size_t)dir * T_SEQ + t) * N_TOT) * HID;
#pragma unroll
        for (int it = 0; it < 2; it++) {
            int l = it * NTHREADS + tid;
            if (l >= 512) break;
            int nl = l >> 2, seg = l & 3;
            int n = n0 + nl;
            int jb = seg * 8;
            float v[8];
#pragma unroll
            for (int q = 0; q < 8; q++) v[q] = D2[((jb + q) * 3) * 132 + nl];
#pragma unroll
            for (int q = 0; q < 8; q++) {
                int j = jt * 32 + jb + q;
                if (j < HID) tupp[(size_t)n * HID + j] = v[q];
            }
            __nv_bfloat16 hi[8], lo[8];
#pragma unroll
            for (int q = 0; q < 8; q++) {
                hi[q] = __float2bfloat16(v[q]);
                lo[q] = __float2bfloat16(v[q] - __bfloat162float(hi[q]));
            }
            uint4 vh, vl;
            vh.x = pack2(hi[0], hi[1]); vh.y = pack2(hi[2], hi[3]);
            vh.z = pack2(hi[4], hi[5]); vh.w = pack2(hi[6], hi[7]);
            vl.x = pack2(lo[0], lo[1]); vl.y = pack2(lo[2], lo[3]);
            vl.z = pack2(lo[4], lo[5]); vl.w = pack2(lo[6], lo[7]);
            *(uint4 *)(hbo + (size_t)n * 256 + jt * 32 + jb) = vh;
            *(uint4 *)(hbo + (size_t)N_TOT * 256 + (size_t)n * 256 + jt * 32 + jb) = vl;
        }
    }
}

// ---------------- word-level attention ----------------
__global__ void __launch_bounds__(256) attn_kernel(const float *__restrict__ att_w) {
    const int n = blockIdx.x;
    const int tid = threadIdx.x;
    __shared__ float xsum[HID];
    __shared__ float red[8];
    __shared__ float s_bc;
    float acc = 0.f, m = -1e30f, denom = 0.f;
    float w = (tid < HID) ? att_w[tid] : 0.f;
    for (int t = 0; t < T_SEQ; t++) {
        if (tid < HID) {
            size_t i0 = (((size_t)0 * T_SEQ + t) * N_TOT + n) * HID + tid;
            size_t i1 = (((size_t)1 * T_SEQ + t) * N_TOT + n) * HID + tid;
            xsum[tid] = g_tup[i0] + g_tup[i1];
        }
        __syncthreads();
        float part = (tid < HID) ? tanhf(xsum[tid]) * w : 0.f;
#pragma unroll
        for (int o = 16; o > 0; o >>= 1) part += __shfl_down_sync(0xffffffffu, part, o);
        if ((tid & 31) == 0) red[tid >> 5] = part;
        __syncthreads();
        if (tid == 0) {
            float sm = 0.f;
#pragma unroll
            for (int q = 0; q < 8; q++) sm += red[q];
            s_bc = sm;
        }
        __syncthreads();
        float st = s_bc;
        float mn = fmaxf(m, st);
        float cc = expf(m - mn), e = expf(st - mn);
        denom = denom * cc + e;
        if (tid < HID) acc = acc * cc + e * xsum[tid];
        m = mn;
        __syncthreads();
    }
    if (tid < HID) g_repre[n * HID + tid] = tanhf(acc / denom);
}

// ---------------- bag attention ----------------
__global__ void __launch_bounds__(256) bag_kernel(const float *__restrict__ sen_a,
                                                  const float *__restrict__ sen_r) {
    const int b = blockIdx.x;
    const int tid = threadIdx.x;
    __shared__ float R[BAGSZ][HID];
    __shared__ float sv[BAGSZ];
    __shared__ float alpha[BAGSZ];
    for (int l = tid; l < BAGSZ * HID; l += 256) {
        int i = l / HID, j = l % HID;
        R[i][j] = g_repre[(b * BAGSZ + i) * HID + j];
    }
    __syncthreads();
    int wid = tid >> 5, lane = tid & 31;
    for (int i = wid; i < BAGSZ; i += 8) {
        float p = 0.f;
        for (int j = lane; j < HID; j += 32) p += R[i][j] * sen_a[j] * sen_r[j];
#pragma unroll
        for (int o = 16; o > 0; o >>= 1) p += __shfl_down_sync(0xffffffffu, p, o);
        if (lane == 0) sv[i] = p;
    }
    __syncthreads();
    if (tid == 0) {
        float mm = -1e30f;
        for (int i = 0; i < BAGSZ; i++) mm = fmaxf(mm, sv[i]);
        float ss = 0.f;
        for (int i = 0; i < BAGSZ; i++) { float e = expf(sv[i] - mm); alpha[i] = e; ss += e; }
        for (int i = 0; i < BAGSZ; i++) alpha[i] /= ss;
    }
    __syncthreads();
    for (int j = tid; j < HID; j += 256) {
        float a = 0.f;
#pragma unroll 4
        for (int i = 0; i < BAGSZ; i++) a += alpha[i] * R[i][j];
        g_sen_s[b * HID + j] = a;
    }
}

// ---------------- logits / prob / bce / acc ----------------
__global__ void __launch_bounds__(128) logits_kernel(const float *__restrict__ rel,
                                                     const float *__restrict__ sen_d,
                                                     const float *__restrict__ y,
                                                     float *__restrict__ out) {
    const int b = blockIdx.x;
    const int tid = threadIdx.x;
    __shared__ float ss[HID];
    __shared__ float lg[NREL];
    __shared__ float mmax;
    __shared__ int amax;
    __shared__ float dsum;
    for (int j = tid; j < HID; j += 128) ss[j] = g_sen_s[b * HID + j];
    __syncthreads();
    if (tid < NREL) {
        float a = sen_d[tid];
        const float *row = rel + (size_t)tid * HID;
        for (int j = 0; j < HID; j++) a += ss[j] * row[j];
        lg[tid] = a;
    }
    __syncthreads();
    if (tid == 0) {
        float mm = lg[0]; int am = 0;
        for (int c = 1; c < NREL; c++) if (lg[c] > mm) { mm = lg[c]; am = c; }
        mmax = mm; amax = am;
        float sum = 0.f;
        for (int c = 0; c < NREL; c++) sum += expf(lg[c] - mm);
        dsum = sum;
    }
    __syncthreads();
    if (tid < NREL) out[1 + NBAG + b * NREL + tid] = expf(lg[tid] - mmax) / dsum;
    if (tid == 0) {
        float loss = 0.f; int lab = 0;
        for (int c = 0; c < NREL; c++) {
            float l = lg[c], yv = y[b * NREL + c];
            loss += fmaxf(l, 0.f) - l * yv + log1pf(expf(-fabsf(l)));
            if (yv > 0.5f) lab = c;
        }
        g_loss_part[b] = loss / (float)NREL;
        out[1 + b] = (amax == lab) ? 1.f : 0.f;
    }
}

__global__ void loss_sum_kernel(float *__restrict__ out) {
    if (threadIdx.x == 0) {
        float s = 0.f;
        for (int b = 0; b < NBAG; b++) s += g_loss_part[b];
        out[0] = s;
    }
}

// ---------------- launch ----------------
extern "C" void kernel_launch(void *const *d_in, const int *in_sizes, int n_in,
                              void *d_out, int out_size) {
    const int *sentence = (const int *)d_in[0];
    const int *pos1 = (const int *)d_in[1];
    const int *pos2 = (const int *)d_in[2];
    const float *y_batch = (const float *)d_in[4];
    const float *word_emb = (const float *)d_in[5];
    const float *p1t = (const float *)d_in[6];
    const float *p2t = (const float *)d_in[7];
    const float *Wihf = (const float *)d_in[8];
    const float *Whhf = (const float *)d_in[9];
    const float *bihf = (const float *)d_in[10];
    const float *bhhf = (const float *)d_in[11];
    const float *Wihb = (const float *)d_in[12];
    const float *Whhb = (const float *)d_in[13];
    const float *bihb = (const float *)d_in[14];
    const float *bhhb = (const float *)d_in[15];
    const float *attw = (const float *)d_in[16];
    const float *sena = (const float *)d_in[17];
    const float *senr = (const float *)d_in[18];
    const float *rel = (const float *)d_in[19];
    const float *send = (const float *)d_in[20];
    float *out = (float *)d_out;

    cudaFuncSetAttribute(gru_step_kernel, cudaFuncAttributeMaxDynamicSharedMemorySize, SMEM_DYN);

    zero_kernel<<<(int)(((size_t)2 * 2 * 256 * N_TOT + 255) / 256), 256>>>();
    prep_w_kernel<<<(2 * 8 * 10 * 96 * 32 + 255) / 256, 256>>>(Wihf, Whhf, Wihb, Whhb);
    gather_kernel<<<(int)(((size_t)N_TOT * T_SEQ * 64 + 255) / 256), 256>>>(
        sentence, pos1, pos2, word_emb, p1t, p2t);

    dim3 grid(16, 8, 2);
    for (int s = 0; s < T_SEQ; s++) {
        gru_step_kernel<<<grid, NTHREADS, SMEM_DYN>>>(s, bihf, bhhf, bihb, bhhb);
    }

    attn_kernel<<<N_TOT, 256>>>(attw);
    bag_kernel<<<NBAG, 256>>>(sena, senr);
    logits_kernel<<<NBAG, 128>>>(rel, send, y_batch, out);
    loss_sum_kernel<<<1, 32>>>(out);
}

// round 7
// speedup vs baseline: 1.2614x; 1.2614x over previous
#include <cuda_runtime.h>
#include <cuda_bf16.h>
#include <math.h>
#include <stdint.h>

#define N_TOT 2048
#define T_SEQ 70
#define HID   230
#define DIN   60
#define EMB_W 50
#define NBAG  64
#define BAGSZ 32
#define NREL  100

// GRU step: M=128, N=96 (32j x 3 gates), K=320 (2 emb chunks + 8 h chunks of 32)
// stage: A_hi[128*64B] A_lo B_hi[96*64B] B_lo, XOR-swizzled 64B rows (pre-swizzled in gmem)
#define NTHREADS 384
#define STAGE_B  28672
#define A_LO_OFF 8192
#define B_HI_OFF 16384
#define DUMP_OFF (3 * STAGE_B)            // 86016
#define SMEM_DYN (DUMP_OFF + 32 * 132 * 4) // 102912

// ---------------- device scratch (all MMA staging pre-swizzled, chunk-major) ----
__device__ __align__(128) __nv_bfloat16 g_Wt[(size_t)2 * 8 * 2 * 10 * 96 * 32]; // [dir][jt][part][chunk][6KB swz]
__device__ __align__(128) __nv_bfloat16 g_embsp[(size_t)T_SEQ * 2 * 2 * N_TOT * 32]; // [t][part][chunk2][2048*64B swz]
__device__ __align__(128) __nv_bfloat16 g_hbf[(size_t)2 * 2 * 2 * 8 * N_TOT * 32];   // [buf][dir][part][chunk8][2048*64B swz]
__device__ float g_hT[(size_t)2 * 2 * 256 * N_TOT];                               // [buf][dir][j][n]
__device__ float g_tup[(size_t)2 * T_SEQ * N_TOT * HID];                          // [dir][t][n][j]
__device__ float g_repre[N_TOT * HID];
__device__ float g_sen_s[NBAG * HID];
__device__ float g_loss_part[NBAG];

// ---------------- ptx helpers ----------------
__device__ __forceinline__ uint32_t smem_u32(const void *p) {
    uint32_t a;
    asm("{ .reg .u64 t; cvta.to.shared.u64 t, %1; cvt.u32.u64 %0, t; }" : "=r"(a) : "l"(p));
    return a;
}
#define BULK_G2S(dst, src, bytes, mbar)                                               \
    asm volatile(                                                                     \
        "cp.async.bulk.shared::cluster.global.mbarrier::complete_tx::bytes "          \
        "[%0], [%1], %2, [%3];"                                                       \
        :: "r"((uint32_t)(dst)), "l"(src), "r"((uint32_t)(bytes)),                    \
           "r"((uint32_t)(mbar)) : "memory")
#define MBARRIER_INIT(mb, cnt) \
    asm volatile("mbarrier.init.shared.b64 [%0], %1;" :: "r"((uint32_t)(mb)), "r"((uint32_t)(cnt)) : "memory")
#define MBARRIER_EXPECT_TX(mb, tx) \
    asm volatile("mbarrier.arrive.expect_tx.shared.b64 _, [%0], %1;" :: "r"((uint32_t)(mb)), "r"((uint32_t)(tx)) : "memory")
#define FENCE_ASYNC_SHARED() asm volatile("fence.proxy.async.shared::cta;" ::: "memory")
#define MBARRIER_WAIT_PARITY(mb, ph) do {                                             \
    uint32_t _m = (uint32_t)(mb); uint32_t _p = (uint32_t)(ph); uint32_t _d;          \
    asm volatile("{\n\t.reg .pred p;\n\t"                                             \
        "mbarrier.try_wait.parity.acquire.cta.shared::cta.b64 p, [%1], %2;\n\t"       \
        "selp.b32 %0, 1, 0, p;\n\t}" : "=r"(_d) : "r"(_m), "r"(_p) : "memory");       \
    if (!_d) {                                                                        \
        asm volatile("{\n\t.reg .pred P1;\n\t"                                        \
            "WL_%=:\n\t"                                                              \
            "mbarrier.try_wait.parity.acquire.cta.shared::cta.b64 P1, [%0], %1, 0x989680;\n\t" \
            "@P1 bra.uni WD_%=;\n\tbra.uni WL_%=;\n\tWD_%=:\n\t}"                     \
            :: "r"(_m), "r"(_p) : "memory");                                          \
    }                                                                                 \
} while (0)
#define LDSM4(r, a)                                                                   \
    asm volatile("ldmatrix.sync.aligned.m8n8.x4.shared.b16 {%0,%1,%2,%3}, [%4];"      \
                 : "=r"((r)[0]), "=r"((r)[1]), "=r"((r)[2]), "=r"((r)[3]) : "r"(a))
#define MMA16816(c, a, b0, b1)                                                        \
    asm volatile("mma.sync.aligned.m16n8k16.row.col.f32.bf16.bf16.f32 "               \
                 "{%0,%1,%2,%3},{%4,%5,%6,%7},{%8,%9},{%0,%1,%2,%3};"                 \
                 : "+f"((c)[0]), "+f"((c)[1]), "+f"((c)[2]), "+f"((c)[3])             \
                 : "r"((a)[0]), "r"((a)[1]), "r"((a)[2]), "r"((a)[3]), "r"(b0), "r"(b1))

__device__ __forceinline__ uint32_t pack2(__nv_bfloat16 a, __nv_bfloat16 b) {
    unsigned short ra = *(unsigned short *)&a, rb = *(unsigned short *)&b;
    return (uint32_t)ra | ((uint32_t)rb << 16);
}
// swizzled byte offset: 64B rows, 16B segs permuted within 8-row (512B) blocks
__device__ __forceinline__ uint32_t swz(int row, int seg) {
    return (uint32_t)row * 64u + (uint32_t)((seg ^ ((row >> 1) & 3)) << 4);
}
// per-element (2B) swizzled bf16 index within a region of 64B rows
__device__ __forceinline__ uint32_t swz_elem(int row, int kc) {
    return (swz(row, kc >> 3) + (uint32_t)(kc & 7) * 2u) >> 1;
}

// ---------------- prep kernels ----------------
__global__ void zero_kernel() {
    size_t i = (size_t)blockIdx.x * blockDim.x + threadIdx.x;
    size_t nh = (size_t)2 * 2 * 2 * 8 * N_TOT * 32 / 2;
    if (i < nh) ((uint32_t *)g_hbf)[i] = 0u;
    if (i < (size_t)2 * 2 * 256 * N_TOT) g_hT[i] = 0.f;
}

// weights -> [dir][jt][part][chunk(10)] contiguous 6144B swizzled; row = j_local*3+gate
__global__ void prep_w_kernel(const float *__restrict__ Wihf, const float *__restrict__ Whhf,
                              const float *__restrict__ Wihb, const float *__restrict__ Whhb) {
    int idx = blockIdx.x * blockDim.x + threadIdx.x;
    if (idx >= 2 * 8 * 10 * 96 * 32) return;
    int kc = idx & 31;
    int r = (idx >> 5) % 96;
    int rest = idx / (96 * 32);
    int c = rest % 10;
    int jt = (rest / 10) & 7;
    int dir = rest / 80;
    const float *Wih = dir ? Wihb : Wihf;
    const float *Whh = dir ? Whhb : Whhf;
    int j = jt * 32 + r / 3;
    int g = r % 3;
    float v = 0.f;
    if (j < HID) {
        if (c < 2) {
            int k = c * 32 + kc;
            if (k < DIN) v = Wih[(g * HID + j) * DIN + k];
        } else {
            int kh = (c - 2) * 32 + kc;
            if (kh < HID) v = Whh[(g * HID + j) * HID + kh];
        }
    }
    __nv_bfloat16 hi = __float2bfloat16(v);
    __nv_bfloat16 lo = __float2bfloat16(v - __bfloat162float(hi));
    uint32_t off = swz_elem(r, kc);
    size_t b0 = (((size_t)(dir * 8 + jt) * 2 + 0) * 10 + c) * (96 * 32);
    size_t b1 = (((size_t)(dir * 8 + jt) * 2 + 1) * 10 + c) * (96 * 32);
    g_Wt[b0 + off] = hi;
    g_Wt[b1 + off] = lo;
}

__global__ void gather_kernel(const int *__restrict__ sent, const int *__restrict__ p1,
                              const int *__restrict__ p2, const float *__restrict__ wemb,
                              const float *__restrict__ p1t, const float *__restrict__ p2t) {
    size_t idx = (size_t)blockIdx.x * blockDim.x + threadIdx.x;
    if (idx >= (size_t)N_TOT * T_SEQ * 64) return;
    int k = (int)(idx & 63);
    size_t nt = idx >> 6;
    int t = (int)(nt % T_SEQ);
    int n = (int)(nt / T_SEQ);
    float v = 0.f;
    if (k < EMB_W) v = wemb[(size_t)sent[n * T_SEQ + t] * EMB_W + k];
    else if (k < EMB_W + 5) v = p1t[p1[n * T_SEQ + t] * 5 + (k - EMB_W)];
    else if (k < DIN) v = p2t[p2[n * T_SEQ + t] * 5 + (k - EMB_W - 5)];
    __nv_bfloat16 hi = __float2bfloat16(v);
    __nv_bfloat16 lo = __float2bfloat16(v - __bfloat162float(hi));
    int chunk = k >> 5, kc = k & 31;
    uint32_t off = swz_elem(n, kc);
    size_t b0 = (((size_t)t * 2 + 0) * 2 + chunk) * (N_TOT * 32);
    size_t b1 = (((size_t)t * 2 + 1) * 2 + chunk) * (N_TOT * 32);
    g_embsp[b0 + off] = hi;
    g_embsp[b1 + off] = lo;
}

// ---------------- GRU step (mma.sync bf16, 3-pass split, bulk-copy pipeline) ----
__global__ void __launch_bounds__(NTHREADS, 2) gru_step_kernel(
    int s,
    const float *__restrict__ bihf, const float *__restrict__ bhhf,
    const float *__restrict__ bihb, const float *__restrict__ bhhb) {
    extern __shared__ char dsm[];
    const int dir = blockIdx.z;
    const int t = dir ? (T_SEQ - 1 - s) : s;
    const int n0 = blockIdx.x * 128;
    const int jt = blockIdx.y;
    const int tid = threadIdx.x;
    const int lane = tid & 31, wid = tid >> 5;
    const int warpM = wid & 3, warpN = wid >> 2;
    const int bufi = s & 1, bufo = (s + 1) & 1;
    const float *bih = dir ? bihb : bihf;
    const float *bhh = dir ? bhhb : bhhf;

    const uint32_t base = smem_u32(dsm);
    float *dumpIN = (float *)(dsm + DUMP_OFF);
    __shared__ float bs[4][32];
    __shared__ __align__(8) unsigned long long mbar[3];
    const uint32_t mb0 = smem_u32(mbar);

    if (tid < 32) {
        int j = jt * 32 + tid;
        bool ok = j < HID;
        bs[0][tid] = ok ? (bih[j] + bhh[j]) : 0.f;
        bs[1][tid] = ok ? (bih[HID + j] + bhh[HID + j]) : 0.f;
        bs[2][tid] = ok ? bih[2 * HID + j] : 0.f;
        bs[3][tid] = ok ? bhh[2 * HID + j] : 0.f;
    }
    if (tid == 0) {
        MBARRIER_INIT(mb0, 1);
        MBARRIER_INIT(mb0 + 8, 1);
        MBARRIER_INIT(mb0 + 16, 1);
        FENCE_ASYNC_SHARED();
    }
    __syncthreads();

    const __nv_bfloat16 *embp = g_embsp + (size_t)t * 2 * 2 * N_TOT * 32 + (size_t)n0 * 32;
    const __nv_bfloat16 *hbfp = g_hbf + (size_t)((bufi * 2 + dir) * 2) * 8 * N_TOT * 32 + (size_t)n0 * 32;
    const __nv_bfloat16 *wbase = g_Wt + (size_t)(dir * 8 + jt) * 2 * 10 * (96 * 32);

    auto arm = [&](int c) {
        uint32_t st = base + (uint32_t)(c % 3) * STAGE_B;
        uint32_t mb = mb0 + (uint32_t)(c % 3) * 8;
        MBARRIER_EXPECT_TX(mb, STAGE_B);
#pragma unroll
        for (int part = 0; part < 2; part++) {
            const __nv_bfloat16 *Ap = (c < 2)
                ? embp + ((size_t)part * 2 + c) * (N_TOT * 32)
                : hbfp + ((size_t)part * 8 + (c - 2)) * (N_TOT * 32);
            BULK_G2S(st + part * A_LO_OFF, Ap, 8192, mb);
            const __nv_bfloat16 *Bp = wbase + ((size_t)part * 10 + c) * (96 * 32);
            BULK_G2S(st + B_HI_OFF + part * 6144, Bp, 6144, mb);
        }
    };

    if (tid == 0) { arm(0); arm(1); }

    float acc[2][4][4];
#pragma unroll
    for (int mi = 0; mi < 2; mi++)
#pragma unroll
        for (int ni = 0; ni < 4; ni++)
#pragma unroll
            for (int q = 0; q < 4; q++) acc[mi][ni][q] = 0.f;

    const int laneR = lane & 15;
    const int laneHi = lane >> 4;
    const int gr = lane >> 2, lc = lane & 3;

    for (int c = 0; c < 10; c++) {
        MBARRIER_WAIT_PARITY(mb0 + (uint32_t)(c % 3) * 8, (c / 3) & 1);
        __syncthreads();                 // all threads done with stage (c-1)%3
        if (c + 2 < 10 && tid == 0) arm(c + 2);
        uint32_t sA = base + (uint32_t)(c % 3) * STAGE_B;
        uint32_t sB = sA + B_HI_OFF;
#pragma unroll
        for (int ks = 0; ks < 2; ks++) {
            uint32_t ah[2][4], al[2][4];
#pragma unroll
            for (int mi = 0; mi < 2; mi++) {
                int row = warpM * 32 + mi * 16 + laneR;
                uint32_t off = swz(row, ks * 2 + laneHi);
                LDSM4(ah[mi], sA + off);
                LDSM4(al[mi], sA + A_LO_OFF + off);
            }
#pragma unroll
            for (int np = 0; np < 2; np++) {
                int row = warpN * 32 + np * 16 + laneR;
                uint32_t off = swz(row, ks * 2 + laneHi);
                uint32_t bh[4], bl[4];
                LDSM4(bh, sB + off);
                LDSM4(bl, sB + 6144 + off);
#pragma unroll
                for (int mi = 0; mi < 2; mi++) {
                    float *c0 = acc[mi][np * 2];
                    float *c1 = acc[mi][np * 2 + 1];
                    MMA16816(c0, ah[mi], bh[0], bh[2]);
                    MMA16816(c0, ah[mi], bl[0], bl[2]);
                    MMA16816(c0, al[mi], bh[0], bh[2]);
                    MMA16816(c1, ah[mi], bh[1], bh[3]);
                    MMA16816(c1, ah[mi], bl[1], bl[3]);
                    MMA16816(c1, al[mi], bh[1], bh[3]);
                }
            }
        }
        if (c == 1) {
            // emb phase done: move i_n slots (col%3==2) to dumpIN, zero them
#pragma unroll
            for (int mi = 0; mi < 2; mi++)
#pragma unroll
                for (int ni = 0; ni < 4; ni++)
#pragma unroll
                    for (int b = 0; b < 2; b++) {
                        int col = warpN * 32 + ni * 8 + lc * 2 + b;
                        if (col % 3 == 2) {
                            int jl = col / 3;
                            int m0 = warpM * 32 + mi * 16 + gr;
                            dumpIN[jl * 132 + m0] = acc[mi][ni][b];
                            dumpIN[jl * 132 + m0 + 8] = acc[mi][ni][b + 2];
                            acc[mi][ni][b] = 0.f;
                            acc[mi][ni][b + 2] = 0.f;
                        }
                    }
        }
    }

    __syncthreads();
    float *D2 = (float *)dsm;   // [96 col][132] (stages idle now)
#pragma unroll
    for (int mi = 0; mi < 2; mi++)
#pragma unroll
        for (int ni = 0; ni < 4; ni++) {
            int col0 = warpN * 32 + ni * 8 + lc * 2;
            int m0 = warpM * 32 + mi * 16 + gr;
            D2[col0 * 132 + m0] = acc[mi][ni][0];
            D2[(col0 + 1) * 132 + m0] = acc[mi][ni][1];
            D2[col0 * 132 + m0 + 8] = acc[mi][ni][2];
            D2[(col0 + 1) * 132 + m0 + 8] = acc[mi][ni][3];
        }
    __syncthreads();

    // gates: 256 work items (32 jl x 8 nsegs of 16)
    if (tid < 256) {
        int jl = tid >> 3, nseg = tid & 7;
        int j = jt * 32 + jl;
        int nb = nseg * 16;
        float br = bs[0][jl], bz = bs[1][jl], bin = bs[2][jl], bhn = bs[3][jl];
        const float4 *holdp = (const float4 *)(g_hT + ((size_t)(bufi * 2 + dir) * 256 + j) * N_TOT + n0 + nb);
        float4 *hnewp = (float4 *)(g_hT + ((size_t)(bufo * 2 + dir) * 256 + j) * N_TOT + n0 + nb);
        const float *Dr = D2 + (jl * 3 + 0) * 132 + nb;
        const float *Dz = D2 + (jl * 3 + 1) * 132 + nb;
        const float *Dn = D2 + (jl * 3 + 2) * 132 + nb;
        const float *Di = dumpIN + jl * 132 + nb;
        float hv[16];
#pragma unroll
        for (int v4 = 0; v4 < 4; v4++) {
            float4 hold4 = holdp[v4];
            float ho[4] = {hold4.x, hold4.y, hold4.z, hold4.w};
            float4 out4;
            float *o = (float *)&out4;
#pragma unroll
            for (int q = 0; q < 4; q++) {
                int i = v4 * 4 + q;
                float r = 1.f / (1.f + expf(-(Dr[i] + br)));
                float z = 1.f / (1.f + expf(-(Dz[i] + bz)));
                float nn = tanhf(Di[i] + bin + r * (Dn[i] + bhn));
                float h = (1.f - z) * nn + z * ho[q];
                hv[i] = h;
                o[q] = h;
            }
            hnewp[v4] = out4;
        }
#pragma unroll
        for (int i = 0; i < 16; i++) D2[(jl * 3) * 132 + nb + i] = hv[i];
    }
    __syncthreads();

    // writeout: tup fp32 [n][j]; h bf16 hi/lo chunk-major pre-swizzled; 512 items
    {
        __nv_bfloat16 *hb0 = g_hbf + ((((size_t)(bufo * 2 + dir) * 2 + 0) * 8 + jt) * N_TOT) * 32;
        __nv_bfloat16 *hb1 = g_hbf + ((((size_t)(bufo * 2 + dir) * 2 + 1) * 8 + jt) * N_TOT) * 32;
        float *tupp = g_tup + (((size_t)dir * T_SEQ + t) * N_TOT) * HID;
#pragma unroll
        for (int it = 0; it < 2; it++) {
            int l = it * NTHREADS + tid;
            if (l >= 512) break;
            int nl = l >> 2, seg = l & 3;
            int n = n0 + nl;
            int jb = seg * 8;
            float v[8];
#pragma unroll
            for (int q = 0; q < 8; q++) v[q] = D2[((jb + q) * 3) * 132 + nl];
#pragma unroll
            for (int q = 0; q < 8; q++) {
                int j = jt * 32 + jb + q;
                if (j < HID) tupp[(size_t)n * HID + j] = v[q];
            }
            __nv_bfloat16 hi[8], lo[8];
#pragma unroll
            for (int q = 0; q < 8; q++) {
                hi[q] = __float2bfloat16(v[q]);
                lo[q] = __float2bfloat16(v[q] - __bfloat162float(hi[q]));
            }
            uint4 vh, vl;
            vh.x = pack2(hi[0], hi[1]); vh.y = pack2(hi[2], hi[3]);
            vh.z = pack2(hi[4], hi[5]); vh.w = pack2(hi[6], hi[7]);
            vl.x = pack2(lo[0], lo[1]); vl.y = pack2(lo[2], lo[3]);
            vl.z = pack2(lo[4], lo[5]); vl.w = pack2(lo[6], lo[7]);
            uint32_t off = swz(n, seg);   // (n>>1)&3 == (nl>>1)&3 since n0 % 128 == 0
            *(uint4 *)((char *)hb0 + off) = vh;
            *(uint4 *)((char *)hb1 + off) = vl;
        }
    }
}

// ---------------- word-level attention ----------------
__global__ void __launch_bounds__(256) attn_kernel(const float *__restrict__ att_w) {
    const int n = blockIdx.x;
    const int tid = threadIdx.x;
    __shared__ float xsum[HID];
    __shared__ float red[8];
    __shared__ float s_bc;
    float acc = 0.f, m = -1e30f, denom = 0.f;
    float w = (tid < HID) ? att_w[tid] : 0.f;
    for (int t = 0; t < T_SEQ; t++) {
        if (tid < HID) {
            size_t i0 = (((size_t)0 * T_SEQ + t) * N_TOT + n) * HID + tid;
            size_t i1 = (((size_t)1 * T_SEQ + t) * N_TOT + n) * HID + tid;
            xsum[tid] = g_tup[i0] + g_tup[i1];
        }
        __syncthreads();
        float part = (tid < HID) ? tanhf(xsum[tid]) * w : 0.f;
#pragma unroll
        for (int o = 16; o > 0; o >>= 1) part += __shfl_down_sync(0xffffffffu, part, o);
        if ((tid & 31) == 0) red[tid >> 5] = part;
        __syncthreads();
        if (tid == 0) {
            float sm = 0.f;
#pragma unroll
            for (int q = 0; q < 8; q++) sm += red[q];
            s_bc = sm;
        }
        __syncthreads();
        float st = s_bc;
        float mn = fmaxf(m, st);
        float cc = expf(m - mn), e = expf(st - mn);
        denom = denom * cc + e;
        if (tid < HID) acc = acc * cc + e * xsum[tid];
        m = mn;
        __syncthreads();
    }
    if (tid < HID) g_repre[n * HID + tid] = tanhf(acc / denom);
}

// ---------------- bag attention ----------------
__global__ void __launch_bounds__(256) bag_kernel(const float *__restrict__ sen_a,
                                                  const float *__restrict__ sen_r) {
    const int b = blockIdx.x;
    const int tid = threadIdx.x;
    __shared__ float R[BAGSZ][HID];
    __shared__ float sv[BAGSZ];
    __shared__ float alpha[BAGSZ];
    for (int l = tid; l < BAGSZ * HID; l += 256) {
        int i = l / HID, j = l % HID;
        R[i][j] = g_repre[(b * BAGSZ + i) * HID + j];
    }
    __syncthreads();
    int wid = tid >> 5, lane = tid & 31;
    for (int i = wid; i < BAGSZ; i += 8) {
        float p = 0.f;
        for (int j = lane; j < HID; j += 32) p += R[i][j] * sen_a[j] * sen_r[j];
#pragma unroll
        for (int o = 16; o > 0; o >>= 1) p += __shfl_down_sync(0xffffffffu, p, o);
        if (lane == 0) sv[i] = p;
    }
    __syncthreads();
    if (tid == 0) {
        float mm = -1e30f;
        for (int i = 0; i < BAGSZ; i++) mm = fmaxf(mm, sv[i]);
        float ss = 0.f;
        for (int i = 0; i < BAGSZ; i++) { float e = expf(sv[i] - mm); alpha[i] = e; ss += e; }
        for (int i = 0; i < BAGSZ; i++) alpha[i] /= ss;
    }
    __syncthreads();
    for (int j = tid; j < HID; j += 256) {
        float a = 0.f;
#pragma unroll 4
        for (int i = 0; i < BAGSZ; i++) a += alpha[i] * R[i][j];
        g_sen_s[b * HID + j] = a;
    }
}

// ---------------- logits / prob / bce / acc ----------------
__global__ void __launch_bounds__(128) logits_kernel(const float *__restrict__ rel,
                                                     const float *__restrict__ sen_d,
                                                     const float *__restrict__ y,
                                                     float *__restrict__ out) {
    const int b = blockIdx.x;
    const int tid = threadIdx.x;
    __shared__ float ss[HID];
    __shared__ float lg[NREL];
    __shared__ float mmax;
    __shared__ int amax;
    __shared__ float dsum;
    for (int j = tid; j < HID; j += 128) ss[j] = g_sen_s[b * HID + j];
    __syncthreads();
    if (tid < NREL) {
        float a = sen_d[tid];
        const float *row = rel + (size_t)tid * HID;
        for (int j = 0; j < HID; j++) a += ss[j] * row[j];
        lg[tid] = a;
    }
    __syncthreads();
    if (tid == 0) {
        float mm = lg[0]; int am = 0;
        for (int c = 1; c < NREL; c++) if (lg[c] > mm) { mm = lg[c]; am = c; }
        mmax = mm; amax = am;
        float sum = 0.f;
        for (int c = 0; c < NREL; c++) sum += expf(lg[c] - mm);
        dsum = sum;
    }
    __syncthreads();
    if (tid < NREL) out[1 + NBAG + b * NREL + tid] = expf(lg[tid] - mmax) / dsum;
    if (tid == 0) {
        float loss = 0.f; int lab = 0;
        for (int c = 0; c < NREL; c++) {
            float l = lg[c], yv = y[b * NREL + c];
            loss += fmaxf(l, 0.f) - l * yv + log1pf(expf(-fabsf(l)));
            if (yv > 0.5f) lab = c;
        }
        g_loss_part[b] = loss / (float)NREL;
        out[1 + b] = (amax == lab) ? 1.f : 0.f;
    }
}

__global__ void loss_sum_kernel(float *__restrict__ out) {
    if (threadIdx.x == 0) {
        float s = 0.f;
        for (int b = 0; b < NBAG; b++) s += g_loss_part[b];
        out[0] = s;
    }
}

// ---------------- launch ----------------
extern "C" void kernel_launch(void *const *d_in, const int *in_sizes, int n_in,
                              void *d_out, int out_size) {
    const int *sentence = (const int *)d_in[0];
    const int *pos1 = (const int *)d_in[1];
    const int *pos2 = (const int *)d_in[2];
    const float *y_batch = (const float *)d_in[4];
    const float *word_emb = (const float *)d_in[5];
    const float *p1t = (const float *)d_in[6];
    const float *p2t = (const float *)d_in[7];
    const float *Wihf = (const float *)d_in[8];
    const float *Whhf = (const float *)d_in[9];
    const float *bihf = (const float *)d_in[10];
    const float *bhhf = (const float *)d_in[11];
    const float *Wihb = (const float *)d_in[12];
    const float *Whhb = (const float *)d_in[13];
    const float *bihb = (const float *)d_in[14];
    const float *bhhb = (const float *)d_in[15];
    const float *attw = (const float *)d_in[16];
    const float *sena = (const float *)d_in[17];
    const float *senr = (const float *)d_in[18];
    const float *rel = (const float *)d_in[19];
    const float *send = (const float *)d_in[20];
    float *out = (float *)d_out;

    cudaFuncSetAttribute(gru_step_kernel, cudaFuncAttributeMaxDynamicSharedMemorySize, SMEM_DYN);

    zero_kernel<<<(int)(((size_t)2 * 2 * 2 * 8 * N_TOT * 32 / 2 + 255) / 256), 256>>>();
    prep_w_kernel<<<(2 * 8 * 10 * 96 * 32 + 255) / 256, 256>>>(Wihf, Whhf, Wihb, Whhb);
    gather_kernel<<<(int)(((size_t)N_TOT * T_SEQ * 64 + 255) / 256), 256>>>(
        sentence, pos1, pos2, word_emb, p1t, p2t);

    dim3 grid(16, 8, 2);
    for (int s = 0; s < T_SEQ; s++) {
        gru_step_kernel<<<grid, NTHREADS, SMEM_DYN>>>(s, bihf, bhhf, bihb, bhhb);
    }

    attn_kernel<<<N_TOT, 256>>>(attw);
    bag_kernel<<<NBAG, 256>>>(sena, senr);
    logits_kernel<<<NBAG, 128>>>(rel, send, y_batch, out);
    loss_sum_kernel<<<1, 32>>>(out);
}

// round 8
// speedup vs baseline: 1.2906x; 1.0231x over previous
#include <cuda_runtime.h>
#include <cuda_bf16.h>
#include <math.h>
#include <stdint.h>

#define N_TOT 2048
#define T_SEQ 70
#define HID   230
#define DIN   60
#define EMB_W 50
#define NBAG  64
#define BAGSZ 32
#define NREL  100

// GRU step: M=128, N=96 (32j x 3 gates), K=320 (2 emb chunks + 8 h chunks of 32)
// stage: A_hi[128*64B] A_lo B_hi[96*64B] B_lo, XOR-swizzled 64B rows (pre-swizzled in gmem)
#define NTHREADS 384
#define STAGE_B  28672
#define A_LO_OFF 8192
#define B_HI_OFF 16384
#define DUMP_OFF (3 * STAGE_B)            // 86016
#define SMEM_DYN (DUMP_OFF + 32 * 132 * 4) // 102912

// ---------------- device scratch (all MMA staging pre-swizzled, chunk-major) ----
__device__ __align__(128) __nv_bfloat16 g_Wt[(size_t)2 * 8 * 2 * 10 * 96 * 32]; // [dir][jt][part][chunk][6KB swz]
__device__ __align__(128) __nv_bfloat16 g_embsp[(size_t)T_SEQ * 2 * 2 * N_TOT * 32]; // [t][part][chunk2][2048*64B swz]
__device__ __align__(128) __nv_bfloat16 g_hbf[(size_t)2 * 2 * 2 * 8 * N_TOT * 32];   // [buf][dir][part][chunk8][2048*64B swz]
__device__ float g_hT[(size_t)2 * 2 * 256 * N_TOT];                               // [buf][dir][j][n]
__device__ float g_tup[(size_t)2 * T_SEQ * N_TOT * HID];                          // [dir][t][n][j]
__device__ float g_repre[N_TOT * HID];
__device__ float g_sen_s[NBAG * HID];
__device__ float g_loss_part[NBAG];

// ---------------- ptx helpers ----------------
__device__ __forceinline__ uint32_t smem_u32(const void *p) {
    uint32_t a;
    asm("{ .reg .u64 t; cvta.to.shared.u64 t, %1; cvt.u32.u64 %0, t; }" : "=r"(a) : "l"(p));
    return a;
}
#define BULK_G2S(dst, src, bytes, mbar)                                               \
    asm volatile(                                                                     \
        "cp.async.bulk.shared::cluster.global.mbarrier::complete_tx::bytes "          \
        "[%0], [%1], %2, [%3];"                                                       \
        :: "r"((uint32_t)(dst)), "l"(src), "r"((uint32_t)(bytes)),                    \
           "r"((uint32_t)(mbar)) : "memory")
#define MBARRIER_INIT(mb, cnt) \
    asm volatile("mbarrier.init.shared.b64 [%0], %1;" :: "r"((uint32_t)(mb)), "r"((uint32_t)(cnt)) : "memory")
#define MBARRIER_EXPECT_TX(mb, tx) \
    asm volatile("mbarrier.arrive.expect_tx.shared.b64 _, [%0], %1;" :: "r"((uint32_t)(mb)), "r"((uint32_t)(tx)) : "memory")
#define MBARRIER_ARRIVE(mb) \
    asm volatile("mbarrier.arrive.shared.b64 _, [%0];" :: "r"((uint32_t)(mb)) : "memory")
#define FENCE_ASYNC_SHARED() asm volatile("fence.proxy.async.shared::cta;" ::: "memory")
#define MBARRIER_WAIT_PARITY(mb, ph) do {                                             \
    uint32_t _m = (uint32_t)(mb); uint32_t _p = (uint32_t)(ph); uint32_t _d;          \
    asm volatile("{\n\t.reg .pred p;\n\t"                                             \
        "mbarrier.try_wait.parity.acquire.cta.shared::cta.b64 p, [%1], %2;\n\t"       \
        "selp.b32 %0, 1, 0, p;\n\t}" : "=r"(_d) : "r"(_m), "r"(_p) : "memory");       \
    if (!_d) {                                                                        \
        asm volatile("{\n\t.reg .pred P1;\n\t"                                        \
            "WL_%=:\n\t"                                                              \
            "mbarrier.try_wait.parity.acquire.cta.shared::cta.b64 P1, [%0], %1, 0x989680;\n\t" \
            "@P1 bra.uni WD_%=;\n\tbra.uni WL_%=;\n\tWD_%=:\n\t}"                     \
            :: "r"(_m), "r"(_p) : "memory");                                          \
    }                                                                                 \
} while (0)
#define LDSM4(r, a)                                                                   \
    asm volatile("ldmatrix.sync.aligned.m8n8.x4.shared.b16 {%0,%1,%2,%3}, [%4];"      \
                 : "=r"((r)[0]), "=r"((r)[1]), "=r"((r)[2]), "=r"((r)[3]) : "r"(a))
#define MMA16816(c, a, b0, b1)                                                        \
    asm volatile("mma.sync.aligned.m16n8k16.row.col.f32.bf16.bf16.f32 "               \
                 "{%0,%1,%2,%3},{%4,%5,%6,%7},{%8,%9},{%0,%1,%2,%3};"                 \
                 : "+f"((c)[0]), "+f"((c)[1]), "+f"((c)[2]), "+f"((c)[3])             \
                 : "r"((a)[0]), "r"((a)[1]), "r"((a)[2]), "r"((a)[3]), "r"(b0), "r"(b1))

__device__ __forceinline__ uint32_t pack2(__nv_bfloat16 a, __nv_bfloat16 b) {
    unsigned short ra = *(unsigned short *)&a, rb = *(unsigned short *)&b;
    return (uint32_t)ra | ((uint32_t)rb << 16);
}
// swizzled byte offset: 64B rows, 16B segs permuted within 8-row (512B) blocks
__device__ __forceinline__ uint32_t swz(int row, int seg) {
    return (uint32_t)row * 64u + (uint32_t)((seg ^ ((row >> 1) & 3)) << 4);
}
__device__ __forceinline__ uint32_t swz_elem(int row, int kc) {
    return (swz(row, kc >> 3) + (uint32_t)(kc & 7) * 2u) >> 1;
}

// ---------------- prep kernels ----------------
__global__ void zero_kernel() {
    size_t i = (size_t)blockIdx.x * blockDim.x + threadIdx.x;
    size_t nh = (size_t)2 * 2 * 2 * 8 * N_TOT * 32 / 2;
    if (i < nh) ((uint32_t *)g_hbf)[i] = 0u;
    if (i < (size_t)2 * 2 * 256 * N_TOT) g_hT[i] = 0.f;
}

__global__ void prep_w_kernel(const float *__restrict__ Wihf, const float *__restrict__ Whhf,
                              const float *__restrict__ Wihb, const float *__restrict__ Whhb) {
    int idx = blockIdx.x * blockDim.x + threadIdx.x;
    if (idx >= 2 * 8 * 10 * 96 * 32) return;
    int kc = idx & 31;
    int r = (idx >> 5) % 96;
    int rest = idx / (96 * 32);
    int c = rest % 10;
    int jt = (rest / 10) & 7;
    int dir = rest / 80;
    const float *Wih = dir ? Wihb : Wihf;
    const float *Whh = dir ? Whhb : Whhf;
    int j = jt * 32 + r / 3;
    int g = r % 3;
    float v = 0.f;
    if (j < HID) {
        if (c < 2) {
            int k = c * 32 + kc;
            if (k < DIN) v = Wih[(g * HID + j) * DIN + k];
        } else {
            int kh = (c - 2) * 32 + kc;
            if (kh < HID) v = Whh[(g * HID + j) * HID + kh];
        }
    }
    __nv_bfloat16 hi = __float2bfloat16(v);
    __nv_bfloat16 lo = __float2bfloat16(v - __bfloat162float(hi));
    uint32_t off = swz_elem(r, kc);
    size_t b0 = (((size_t)(dir * 8 + jt) * 2 + 0) * 10 + c) * (96 * 32);
    size_t b1 = (((size_t)(dir * 8 + jt) * 2 + 1) * 10 + c) * (96 * 32);
    g_Wt[b0 + off] = hi;
    g_Wt[b1 + off] = lo;
}

__global__ void gather_kernel(const int *__restrict__ sent, const int *__restrict__ p1,
                              const int *__restrict__ p2, const float *__restrict__ wemb,
                              const float *__restrict__ p1t, const float *__restrict__ p2t) {
    size_t idx = (size_t)blockIdx.x * blockDim.x + threadIdx.x;
    if (idx >= (size_t)N_TOT * T_SEQ * 64) return;
    int k = (int)(idx & 63);
    size_t nt = idx >> 6;
    int t = (int)(nt % T_SEQ);
    int n = (int)(nt / T_SEQ);
    float v = 0.f;
    if (k < EMB_W) v = wemb[(size_t)sent[n * T_SEQ + t] * EMB_W + k];
    else if (k < EMB_W + 5) v = p1t[p1[n * T_SEQ + t] * 5 + (k - EMB_W)];
    else if (k < DIN) v = p2t[p2[n * T_SEQ + t] * 5 + (k - EMB_W - 5)];
    __nv_bfloat16 hi = __float2bfloat16(v);
    __nv_bfloat16 lo = __float2bfloat16(v - __bfloat162float(hi));
    int chunk = k >> 5, kc = k & 31;
    uint32_t off = swz_elem(n, kc);
    size_t b0 = (((size_t)t * 2 + 0) * 2 + chunk) * (N_TOT * 32);
    size_t b1 = (((size_t)t * 2 + 1) * 2 + chunk) * (N_TOT * 32);
    g_embsp[b0 + off] = hi;
    g_embsp[b1 + off] = lo;
}

// ---------------- GRU step (bf16 3-pass, bulk pipeline, free-running warps) ----
__global__ void __launch_bounds__(NTHREADS, 2) gru_step_kernel(
    int s,
    const float *__restrict__ bihf, const float *__restrict__ bhhf,
    const float *__restrict__ bihb, const float *__restrict__ bhhb) {
    extern __shared__ char dsm[];
    const int dir = blockIdx.z;
    const int t = dir ? (T_SEQ - 1 - s) : s;
    const int n0 = blockIdx.x * 128;
    const int jt = blockIdx.y;
    const int tid = threadIdx.x;
    const int lane = tid & 31, wid = tid >> 5;
    const int warpM = wid & 3, warpN = wid >> 2;
    const int bufi = s & 1, bufo = (s + 1) & 1;
    const float *bih = dir ? bihb : bihf;
    const float *bhh = dir ? bhhb : bhhf;

    const uint32_t base = smem_u32(dsm);
    float *dumpIN = (float *)(dsm + DUMP_OFF);
    __shared__ float bs[4][32];
    __shared__ __align__(8) unsigned long long mbar[6];   // full[3], empty[3]
    const uint32_t mbF = smem_u32(mbar);
    const uint32_t mbE = mbF + 24;

    if (tid < 32) {
        int j = jt * 32 + tid;
        bool ok = j < HID;
        bs[0][tid] = ok ? (bih[j] + bhh[j]) : 0.f;
        bs[1][tid] = ok ? (bih[HID + j] + bhh[HID + j]) : 0.f;
        bs[2][tid] = ok ? bih[2 * HID + j] : 0.f;
        bs[3][tid] = ok ? bhh[2 * HID + j] : 0.f;
    }
    if (tid == 0) {
        MBARRIER_INIT(mbF, 1);
        MBARRIER_INIT(mbF + 8, 1);
        MBARRIER_INIT(mbF + 16, 1);
        MBARRIER_INIT(mbE, 12);
        MBARRIER_INIT(mbE + 8, 12);
        MBARRIER_INIT(mbE + 16, 12);
        FENCE_ASYNC_SHARED();
    }
    __syncthreads();

    const __nv_bfloat16 *embp = g_embsp + (size_t)t * 2 * 2 * N_TOT * 32 + (size_t)n0 * 32;
    const __nv_bfloat16 *hbfp = g_hbf + (size_t)((bufi * 2 + dir) * 2) * 8 * N_TOT * 32 + (size_t)n0 * 32;
    const __nv_bfloat16 *wbase = g_Wt + (size_t)(dir * 8 + jt) * 2 * 10 * (96 * 32);

    auto arm = [&](int k) {
        if (k >= 3) MBARRIER_WAIT_PARITY(mbE + (uint32_t)(k % 3) * 8, ((k / 3) + 1) & 1);
        uint32_t st = base + (uint32_t)(k % 3) * STAGE_B;
        uint32_t mb = mbF + (uint32_t)(k % 3) * 8;
        MBARRIER_EXPECT_TX(mb, STAGE_B);
#pragma unroll
        for (int part = 0; part < 2; part++) {
            const __nv_bfloat16 *Ap = (k < 2)
                ? embp + ((size_t)part * 2 + k) * (N_TOT * 32)
                : hbfp + ((size_t)part * 8 + (k - 2)) * (N_TOT * 32);
            BULK_G2S(st + part * A_LO_OFF, Ap, 8192, mb);
            const __nv_bfloat16 *Bp = wbase + ((size_t)part * 10 + k) * (96 * 32);
            BULK_G2S(st + B_HI_OFF + part * 6144, Bp, 6144, mb);
        }
    };

    if (tid == 0) { arm(0); arm(1); }

    float acc[2][4][4];
#pragma unroll
    for (int mi = 0; mi < 2; mi++)
#pragma unroll
        for (int ni = 0; ni < 4; ni++)
#pragma unroll
            for (int q = 0; q < 4; q++) acc[mi][ni][q] = 0.f;

    const int laneR = lane & 15;
    const int laneHi = lane >> 4;
    const int gr = lane >> 2, lc = lane & 3;

    for (int c = 0; c < 10; c++) {
        MBARRIER_WAIT_PARITY(mbF + (uint32_t)(c % 3) * 8, (c / 3) & 1);
        if (tid == 0 && c + 2 < 10) arm(c + 2);
        uint32_t sA = base + (uint32_t)(c % 3) * STAGE_B;
        uint32_t sB = sA + B_HI_OFF;
#pragma unroll
        for (int ks = 0; ks < 2; ks++) {
            uint32_t ah[2][4], al[2][4];
#pragma unroll
            for (int mi = 0; mi < 2; mi++) {
                int row = warpM * 32 + mi * 16 + laneR;
                uint32_t off = swz(row, ks * 2 + laneHi);
                LDSM4(ah[mi], sA + off);
                LDSM4(al[mi], sA + A_LO_OFF + off);
            }
#pragma unroll
            for (int np = 0; np < 2; np++) {
                int row = warpN * 32 + np * 16 + laneR;
                uint32_t off = swz(row, ks * 2 + laneHi);
                uint32_t bh[4], bl[4];
                LDSM4(bh, sB + off);
                LDSM4(bl, sB + 6144 + off);
                // pass-major order: RAW reuse distance = 4 MMAs
#pragma unroll
                for (int pass = 0; pass < 3; pass++) {
                    const uint32_t(*aa)[4] = (pass == 2) ? al : ah;
                    const uint32_t *bb = (pass == 1) ? bl : bh;
#pragma unroll
                    for (int mi = 0; mi < 2; mi++) {
                        MMA16816(acc[mi][np * 2], aa[mi], bb[0], bb[2]);
                        MMA16816(acc[mi][np * 2 + 1], aa[mi], bb[1], bb[3]);
                    }
                }
            }
        }
        if (lane == 0) MBARRIER_ARRIVE(mbE + (uint32_t)(c % 3) * 8);
        if (c == 1) {
            // emb phase done: move i_n slots (col%3==2) to dumpIN, zero them
#pragma unroll
            for (int mi = 0; mi < 2; mi++)
#pragma unroll
                for (int ni = 0; ni < 4; ni++)
#pragma unroll
                    for (int b = 0; b < 2; b++) {
                        int col = warpN * 32 + ni * 8 + lc * 2 + b;
                        if (col % 3 == 2) {
                            int jl = col / 3;
                            int m0 = warpM * 32 + mi * 16 + gr;
                            dumpIN[jl * 132 + m0] = acc[mi][ni][b];
                            dumpIN[jl * 132 + m0 + 8] = acc[mi][ni][b + 2];
                            acc[mi][ni][b] = 0.f;
                            acc[mi][ni][b + 2] = 0.f;
                        }
                    }
        }
    }

    __syncthreads();   // all warps done with stages; reuse for D staging
    float *D2 = (float *)dsm;   // [96 col][132]
#pragma unroll
    for (int mi = 0; mi < 2; mi++)
#pragma unroll
        for (int ni = 0; ni < 4; ni++) {
            int col0 = warpN * 32 + ni * 8 + lc * 2;
            int m0 = warpM * 32 + mi * 16 + gr;
            D2[col0 * 132 + m0] = acc[mi][ni][0];
            D2[(col0 + 1) * 132 + m0] = acc[mi][ni][1];
            D2[col0 * 132 + m0 + 8] = acc[mi][ni][2];
            D2[(col0 + 1) * 132 + m0 + 8] = acc[mi][ni][3];
        }
    __syncthreads();

    // gates: 256 work items (32 jl x 8 nsegs of 16)
    if (tid < 256) {
        int jl = tid >> 3, nseg = tid & 7;
        int j = jt * 32 + jl;
        int nb = nseg * 16;
        float br = bs[0][jl], bz = bs[1][jl], bin = bs[2][jl], bhn = bs[3][jl];
        const float4 *holdp = (const float4 *)(g_hT + ((size_t)(bufi * 2 + dir) * 256 + j) * N_TOT + n0 + nb);
        float4 *hnewp = (float4 *)(g_hT + ((size_t)(bufo * 2 + dir) * 256 + j) * N_TOT + n0 + nb);
        const float *Dr = D2 + (jl * 3 + 0) * 132 + nb;
        const float *Dz = D2 + (jl * 3 + 1) * 132 + nb;
        const float *Dn = D2 + (jl * 3 + 2) * 132 + nb;
        const float *Di = dumpIN + jl * 132 + nb;
        float hv[16];
#pragma unroll
        for (int v4 = 0; v4 < 4; v4++) {
            float4 hold4 = holdp[v4];
            float ho[4] = {hold4.x, hold4.y, hold4.z, hold4.w};
            float4 out4;
            float *o = (float *)&out4;
#pragma unroll
            for (int q = 0; q < 4; q++) {
                int i = v4 * 4 + q;
                float r = 1.f / (1.f + expf(-(Dr[i] + br)));
                float z = 1.f / (1.f + expf(-(Dz[i] + bz)));
                float nn = tanhf(Di[i] + bin + r * (Dn[i] + bhn));
                float h = (1.f - z) * nn + z * ho[q];
                hv[i] = h;
                o[q] = h;
            }
            hnewp[v4] = out4;
        }
#pragma unroll
        for (int i = 0; i < 16; i++) D2[(jl * 3) * 132 + nb + i] = hv[i];
    }
    __syncthreads();

    // writeout: tup fp32 [n][j]; h bf16 hi/lo chunk-major pre-swizzled; 512 items
    {
        __nv_bfloat16 *hb0 = g_hbf + ((((size_t)(bufo * 2 + dir) * 2 + 0) * 8 + jt) * N_TOT) * 32;
        __nv_bfloat16 *hb1 = g_hbf + ((((size_t)(bufo * 2 + dir) * 2 + 1) * 8 + jt) * N_TOT) * 32;
        float *tupp = g_tup + (((size_t)dir * T_SEQ + t) * N_TOT) * HID;
#pragma unroll
        for (int it = 0; it < 2; it++) {
            int l = it * NTHREADS + tid;
            if (l >= 512) break;
            int nl = l >> 2, seg = l & 3;
            int n = n0 + nl;
            int jb = seg * 8;
            float v[8];
#pragma unroll
            for (int q = 0; q < 8; q++) v[q] = D2[((jb + q) * 3) * 132 + nl];
#pragma unroll
            for (int q = 0; q < 8; q++) {
                int j = jt * 32 + jb + q;
                if (j < HID) tupp[(size_t)n * HID + j] = v[q];
            }
            __nv_bfloat16 hi[8], lo[8];
#pragma unroll
            for (int q = 0; q < 8; q++) {
                hi[q] = __float2bfloat16(v[q]);
                lo[q] = __float2bfloat16(v[q] - __bfloat162float(hi[q]));
            }
            uint4 vh, vl;
            vh.x = pack2(hi[0], hi[1]); vh.y = pack2(hi[2], hi[3]);
            vh.z = pack2(hi[4], hi[5]); vh.w = pack2(hi[6], hi[7]);
            vl.x = pack2(lo[0], lo[1]); vl.y = pack2(lo[2], lo[3]);
            vl.z = pack2(lo[4], lo[5]); vl.w = pack2(lo[6], lo[7]);
            uint32_t off = swz(n, seg);
            *(uint4 *)((char *)hb0 + off) = vh;
            *(uint4 *)((char *)hb1 + off) = vl;
        }
    }
}

// ---------------- word-level attention ----------------
__global__ void __launch_bounds__(256) attn_kernel(const float *__restrict__ att_w) {
    const int n = blockIdx.x;
    const int tid = threadIdx.x;
    __shared__ float xsum[HID];
    __shared__ float red[8];
    __shared__ float s_bc;
    float acc = 0.f, m = -1e30f, denom = 0.f;
    float w = (tid < HID) ? att_w[tid] : 0.f;
    for (int t = 0; t < T_SEQ; t++) {
        if (tid < HID) {
            size_t i0 = (((size_t)0 * T_SEQ + t) * N_TOT + n) * HID + tid;
            size_t i1 = (((size_t)1 * T_SEQ + t) * N_TOT + n) * HID + tid;
            xsum[tid] = g_tup[i0] + g_tup[i1];
        }
        __syncthreads();
        float part = (tid < HID) ? tanhf(xsum[tid]) * w : 0.f;
#pragma unroll
        for (int o = 16; o > 0; o >>= 1) part += __shfl_down_sync(0xffffffffu, part, o);
        if ((tid & 31) == 0) red[tid >> 5] = part;
        __syncthreads();
        if (tid == 0) {
            float sm = 0.f;
#pragma unroll
            for (int q = 0; q < 8; q++) sm += red[q];
            s_bc = sm;
        }
        __syncthreads();
        float st = s_bc;
        float mn = fmaxf(m, st);
        float cc = expf(m - mn), e = expf(st - mn);
        denom = denom * cc + e;
        if (tid < HID) acc = acc * cc + e * xsum[tid];
        m = mn;
        __syncthreads();
    }
    if (tid < HID) g_repre[n * HID + tid] = tanhf(acc / denom);
}

// ---------------- bag attention ----------------
__global__ void __launch_bounds__(256) bag_kernel(const float *__restrict__ sen_a,
                                                  const float *__restrict__ sen_r) {
    const int b = blockIdx.x;
    const int tid = threadIdx.x;
    __shared__ float R[BAGSZ][HID];
    __shared__ float sv[BAGSZ];
    __shared__ float alpha[BAGSZ];
    for (int l = tid; l < BAGSZ * HID; l += 256) {
        int i = l / HID, j = l % HID;
        R[i][j] = g_repre[(b * BAGSZ + i) * HID + j];
    }
    __syncthreads();
    int wid = tid >> 5, lane = tid & 31;
    for (int i = wid; i < BAGSZ; i += 8) {
        float p = 0.f;
        for (int j = lane; j < HID; j += 32) p += R[i][j] * sen_a[j] * sen_r[j];
#pragma unroll
        for (int o = 16; o > 0; o >>= 1) p += __shfl_down_sync(0xffffffffu, p, o);
        if (lane == 0) sv[i] = p;
    }
    __syncthreads();
    if (tid == 0) {
        float mm = -1e30f;
        for (int i = 0; i < BAGSZ; i++) mm = fmaxf(mm, sv[i]);
        float ss = 0.f;
        for (int i = 0; i < BAGSZ; i++) { float e = expf(sv[i] - mm); alpha[i] = e; ss += e; }
        for (int i = 0; i < BAGSZ; i++) alpha[i] /= ss;
    }
    __syncthreads();
    for (int j = tid; j < HID; j += 256) {
        float a = 0.f;
#pragma unroll 4
        for (int i = 0; i < BAGSZ; i++) a += alpha[i] * R[i][j];
        g_sen_s[b * HID + j] = a;
    }
}

// ---------------- logits / prob / bce / acc ----------------
__global__ void __launch_bounds__(128) logits_kernel(const float *__restrict__ rel,
                                                     const float *__restrict__ sen_d,
                                                     const float *__restrict__ y,
                                                     float *__restrict__ out) {
    const int b = blockIdx.x;
    const int tid = threadIdx.x;
    __shared__ float ss[HID];
    __shared__ float lg[NREL];
    __shared__ float mmax;
    __shared__ int amax;
    __shared__ float dsum;
    for (int j = tid; j < HID; j += 128) ss[j] = g_sen_s[b * HID + j];
    __syncthreads();
    if (tid < NREL) {
        float a = sen_d[tid];
        const float *row = rel + (size_t)tid * HID;
        for (int j = 0; j < HID; j++) a += ss[j] * row[j];
        lg[tid] = a;
    }
    __syncthreads();
    if (tid == 0) {
        float mm = lg[0]; int am = 0;
        for (int c = 1; c < NREL; c++) if (lg[c] > mm) { mm = lg[c]; am = c; }
        mmax = mm; amax = am;
        float sum = 0.f;
        for (int c = 0; c < NREL; c++) sum += expf(lg[c] - mm);
        dsum = sum;
    }
    __syncthreads();
    if (tid < NREL) out[1 + NBAG + b * NREL + tid] = expf(lg[tid] - mmax) / dsum;
    if (tid == 0) {
        float loss = 0.f; int lab = 0;
        for (int c = 0; c < NREL; c++) {
            float l = lg[c], yv = y[b * NREL + c];
            loss += fmaxf(l, 0.f) - l * yv + log1pf(expf(-fabsf(l)));
            if (yv > 0.5f) lab = c;
        }
        g_loss_part[b] = loss / (float)NREL;
        out[1 + b] = (amax == lab) ? 1.f : 0.f;
    }
}

__global__ void loss_sum_kernel(float *__restrict__ out) {
    if (threadIdx.x == 0) {
        float s = 0.f;
        for (int b = 0; b < NBAG; b++) s += g_loss_part[b];
        out[0] = s;
    }
}

// ---------------- launch ----------------
extern "C" void kernel_launch(void *const *d_in, const int *in_sizes, int n_in,
                              void *d_out, int out_size) {
    const int *sentence = (const int *)d_in[0];
    const int *pos1 = (const int *)d_in[1];
    const int *pos2 = (const int *)d_in[2];
    const float *y_batch = (const float *)d_in[4];
    const float *word_emb = (const float *)d_in[5];
    const float *p1t = (const float *)d_in[6];
    const float *p2t = (const float *)d_in[7];
    const float *Wihf = (const float *)d_in[8];
    const float *Whhf = (const float *)d_in[9];
    const float *bihf = (const float *)d_in[10];
    const float *bhhf = (const float *)d_in[11];
    const float *Wihb = (const float *)d_in[12];
    const float *Whhb = (const float *)d_in[13];
    const float *bihb = (const float *)d_in[14];
    const float *bhhb = (const float *)d_in[15];
    const float *attw = (const float *)d_in[16];
    const float *sena = (const float *)d_in[17];
    const float *senr = (const float *)d_in[18];
    const float *rel = (const float *)d_in[19];
    const float *send = (const float *)d_in[20];
    float *out = (float *)d_out;

    cudaFuncSetAttribute(gru_step_kernel, cudaFuncAttributeMaxDynamicSharedMemorySize, SMEM_DYN);

    zero_kernel<<<(int)(((size_t)2 * 2 * 2 * 8 * N_TOT * 32 / 2 + 255) / 256), 256>>>();
    prep_w_kernel<<<(2 * 8 * 10 * 96 * 32 + 255) / 256, 256>>>(Wihf, Whhf, Wihb, Whhb);
    gather_kernel<<<(int)(((size_t)N_TOT * T_SEQ * 64 + 255) / 256), 256>>>(
        sentence, pos1, pos2, word_emb, p1t, p2t);

    dim3 grid(16, 8, 2);
    for (int s = 0; s < T_SEQ; s++) {
        gru_step_kernel<<<grid, NTHREADS, SMEM_DYN>>>(s, bihf, bhhf, bihb, bhhb);
    }

    attn_kernel<<<N_TOT, 256>>>(attw);
    bag_kernel<<<NBAG, 256>>>(sena, senr);
    logits_kernel<<<NBAG, 128>>>(rel, send, y_batch, out);
    loss_sum_kernel<<<1, 32>>>(out);
}